// round 6
// baseline (speedup 1.0000x reference)
#include <cuda_runtime.h>
#include <math.h>
#include <stdint.h>

#define BS2   2
#define NN    8192
#define NPT   128
#define CC    128
#define M_TOT 8192        // NPT*64 per batch
#define MG    16384       // total corners

// ---------------- device scratch ----------------
static __device__ float g_p2[(size_t)BS2*NN];
static __device__ float g_rel[(size_t)MG*3];
static __device__ float g_cor[(size_t)MG*3];
static __device__ int   g_nni[(size_t)MG*3];
static __device__ float g_nnw[(size_t)MG*3];
static __device__ float g_w1T[128*128];                 // [k][o]  (W1 feature part, transposed)
static __device__ float g_w2T[128*256];                 // [k][o]
static __device__ float g_G[(size_t)BS2*NN*128];        // [b][n][o] = W1f . f
static __device__ float g_h1T[(size_t)128*MG];          // [c][m]
static __device__ float g_pool[(size_t)BS2*256*NPT];    // [b][o][p]
static __device__ float g_z0[(size_t)BS2*128*NPT];
static __device__ float g_z1[(size_t)BS2*128*NPT];

__device__ __forceinline__ float tf32r(float x) {
    uint32_t u; asm("cvt.rna.tf32.f32 %0, %1;" : "=r"(u) : "f"(x));
    return __uint_as_float(u);
}

__device__ __forceinline__ void mma_tf32(float c[4], const uint32_t a[4], const uint32_t b[2]) {
    asm volatile(
        "mma.sync.aligned.m16n8k8.row.col.f32.tf32.tf32.f32 "
        "{%0,%1,%2,%3}, {%4,%5,%6,%7}, {%8,%9}, {%0,%1,%2,%3};\n"
        : "+f"(c[0]), "+f"(c[1]), "+f"(c[2]), "+f"(c[3])
        : "r"(a[0]), "r"(a[1]), "r"(a[2]), "r"(a[3]), "r"(b[0]), "r"(b[1]));
}

// ---------------- fused setup: decode + p2 + transpose W1f / W2 ----------------
__global__ void setup_kernel(const float* __restrict__ cand,
                             const float* __restrict__ off,
                             const float* __restrict__ acls,
                             const float* __restrict__ ares,
                             const float* __restrict__ oxyz,
                             const float* __restrict__ w1,
                             const float* __restrict__ w2)
{
    int bx = blockIdx.x, tid = threadIdx.x;
    if (bx < 64) {
        int t = bx*256 + tid;                        // 16384 = b*8192 + p*64 + k
        int k  = t & 63;
        int bp = t >> 6;
        const float* a = acls + bp*12;
        float best = a[0]; int bi = 0;
        #pragma unroll
        for (int j = 1; j < 12; j++) { float v = a[j]; if (v > best) { best = v; bi = j; } }
        float res = ares[bp*12 + bi];
        const float PI_F = 3.14159265358979323846f;
        float ang = (float)bi * (float)(2.0*3.14159265358979323846/12.0) + res;
        float heading = (ang > PI_F) ? (ang - 2.0f*PI_F) : ang;
        float s, c; sincosf(heading, &s, &c);
        const float* o6 = off + bp*6;
        float cx = cand[bp*3+0] + o6[0];
        float cy = cand[bp*3+1] + o6[1];
        float cz = cand[bp*3+2] + o6[2];
        float lx = fmaxf(o6[3]*2.0f, 0.1f);
        float ly = fmaxf(o6[4]*2.0f, 0.1f);
        float lz = fmaxf(o6[5]*2.0f, 0.1f);
        float gv[4] = {-1.0f, -1.0f/3.0f, 1.0f/3.0f, 1.0f};
        float gx = gv[(k>>4)&3] * lx;
        float gy = gv[(k>>2)&3] * ly;
        float gz = gv[k&3]      * lz;
        float rx = gx*c - gy*s;
        float ry = gx*s + gy*c;
        float rz = gz;
        size_t b3 = (size_t)t*3;
        g_rel[b3+0] = rx; g_rel[b3+1] = ry; g_rel[b3+2] = rz;
        g_cor[b3+0] = rx + cx; g_cor[b3+1] = ry + cy; g_cor[b3+2] = rz + cz;
    } else if (bx < 128) {
        int t = (bx-64)*256 + tid;
        float x = oxyz[t*3], y = oxyz[t*3+1], z = oxyz[t*3+2];
        g_p2[t] = x*x + y*y + z*z;
    } else if (bx < 192) {
        int t = (bx-128)*256 + tid;                  // 16384 = k*128+o
        int o = t & 127, k = t >> 7;
        g_w1T[t] = w1[o*131 + 3 + k];
    } else {
        int t = (bx-192)*256 + tid;                  // 32768 = k*256+o
        int o = t & 255, k = t >> 8;
        g_w2T[t] = w2[o*128 + k];
    }
}

// ---------------- top-3 merge helper ----------------
__device__ __forceinline__ void merge_write(float d0, float d1, float d2,
                                            int i0, int i1, int i2,
                                            volatile float* mw, volatile int* mi,
                                            int lane, const float* __restrict__ O,
                                            int b, int m, float cx, float cy, float cz)
{
    mw[lane*3+0] = d0; mi[lane*3+0] = i0;
    mw[lane*3+1] = d1; mi[lane*3+1] = i1;
    mw[lane*3+2] = d2; mi[lane*3+2] = i2;
    __syncwarp();
    int win[3];
    #pragma unroll
    for (int r = 0; r < 3; r++) {
        float v = 1e30f; int pos = 1<<30;
        #pragma unroll
        for (int j = 0; j < 3; j++) {
            int jj = lane + 32*j;
            float vv = mw[jj];
            if (vv < v || (vv == v && jj < pos)) { v = vv; pos = jj; }
        }
        #pragma unroll
        for (int offi = 16; offi; offi >>= 1) {
            float v2 = __shfl_xor_sync(0xffffffffu, v, offi);
            int   q2 = __shfl_xor_sync(0xffffffffu, pos, offi);
            if (v2 < v || (v2 == v && q2 < pos)) { v = v2; pos = q2; }
        }
        win[r] = mi[pos];
        if (lane == 0) mw[pos] = 2e30f;
        __syncwarp();
    }
    if (lane == 0) {
        float w[3], ssum = 0.0f;
        #pragma unroll
        for (int r = 0; r < 3; r++) {
            const float* P = O + (size_t)win[r]*3;
            float dx = P[0]-cx, dy = P[1]-cy, dz = P[2]-cz;
            float d = sqrtf(dx*dx + dy*dy + dz*dz);
            w[r] = 1.0f / (d + 1e-8f);
            ssum += w[r];
        }
        size_t base = ((size_t)b*M_TOT + m)*3;
        float inv = 1.0f/ssum;
        #pragma unroll
        for (int r = 0; r < 3; r++) { g_nni[base+r] = win[r]; g_nnw[base+r] = w[r]*inv; }
    }
    __syncwarp();
}

// ---------------- gemmG body (R3-proven config; dynamic smem) ----------------
__device__ __forceinline__ void gemmG_body(const float* __restrict__ feat, int bx, char* smraw)
{
    float* NsB = (float*)smraw;                  // [2][16][132]
    float* OsB = (float*)(smraw + 16896);        // [2][16][64]
    #define NS(bu,k,i) NsB[(((bu)*16)+(k))*132+(i)]
    #define OS(bu,k,i) OsB[(((bu)*16)+(k))*64+(i)]
    int nt = bx & 63, rest = bx >> 6;
    int ot = rest & 1, b = rest >> 1;
    int n0 = nt*128, o0 = ot*64;
    int tid = threadIdx.x;
    int kr  = tid >> 4;
    int nc  = (tid & 15)*8;
    int oc  = (tid & 15)*4;
    int tr  = (tid >> 4)*8;
    int tc  = (tid & 15)*4;
    const float* F = feat + (size_t)b*CC*NN;

    float acc[8][4] = {};
    float4 na0, na1, nb;
    na0 = *(const float4*)&F[(size_t)kr*NN + n0 + nc];
    na1 = *(const float4*)&F[(size_t)kr*NN + n0 + nc + 4];
    nb  = *(const float4*)&g_w1T[kr*128 + o0 + oc];
    *(float4*)&NS(0,kr,nc)   = na0;
    *(float4*)&NS(0,kr,nc+4) = na1;
    *(float4*)&OS(0,kr,oc)   = nb;
    __syncthreads();
    int buf = 0;
    #pragma unroll 1
    for (int kb = 0; kb < 8; kb++) {
        bool has = kb < 7;
        if (has) {
            int kk = (kb+1)*16 + kr;
            na0 = *(const float4*)&F[(size_t)kk*NN + n0 + nc];
            na1 = *(const float4*)&F[(size_t)kk*NN + n0 + nc + 4];
            nb  = *(const float4*)&g_w1T[kk*128 + o0 + oc];
        }
        #pragma unroll
        for (int k = 0; k < 16; k++) {
            float4 a0 = *(const float4*)&NS(buf,k,tr);
            float4 a1 = *(const float4*)&NS(buf,k,tr+4);
            float4 bq = *(const float4*)&OS(buf,k,tc);
            float ar[8] = {a0.x,a0.y,a0.z,a0.w,a1.x,a1.y,a1.z,a1.w};
            float br[4] = {bq.x,bq.y,bq.z,bq.w};
            #pragma unroll
            for (int i = 0; i < 8; i++)
                #pragma unroll
                for (int j = 0; j < 4; j++)
                    acc[i][j] = fmaf(ar[i], br[j], acc[i][j]);
        }
        if (has) {
            int nbuf = buf^1;
            *(float4*)&NS(nbuf,kr,nc)   = na0;
            *(float4*)&NS(nbuf,kr,nc+4) = na1;
            *(float4*)&OS(nbuf,kr,oc)   = nb;
            __syncthreads();
            buf = nbuf;
        }
    }
    float* Gp = g_G + ((size_t)b*NN + n0 + tr)*128 + o0 + tc;
    #pragma unroll
    for (int i = 0; i < 8; i++) {
        float4 v = {acc[i][0], acc[i][1], acc[i][2], acc[i][3]};
        *(float4*)(Gp + (size_t)i*128) = v;
    }
    #undef NS
    #undef OS
}

// ---------------- three_nn body: warp handles 4 corners (dynamic smem) ----------------
__device__ __forceinline__ void three_nn_body(const float* __restrict__ oxyz, int bx, char* smraw)
{
    float4* st = (float4*)smraw;                 // 512 * 16 = 8192
    float*  mwB = (float*)(smraw + 8192);        // 8*96*4
    int*    miB = (int*)(smraw + 8192 + 3072);   // 8*96*4
    int tid = threadIdx.x, lane = tid & 31, wid = tid >> 5;
    int gw = bx*8 + wid;                         // 0..4095
    int b  = gw >> 11;
    int mbase = (gw & 2047) * 4;
    const float* O = oxyz + (size_t)b*NN*3;
    const float* Q = g_p2 + (size_t)b*NN;

    float cx[4], cy[4], cz[4], c2[4], ax[4], ay[4], az[4];
    float bd0[4], bd1[4], bd2[4]; int bi0[4], bi1[4], bi2[4];
    #pragma unroll
    for (int c = 0; c < 4; c++) {
        size_t bb = ((size_t)b*M_TOT + mbase + c)*3;
        cx[c] = g_cor[bb+0]; cy[c] = g_cor[bb+1]; cz[c] = g_cor[bb+2];
        c2[c] = cx[c]*cx[c] + cy[c]*cy[c] + cz[c]*cz[c];
        ax[c] = -2.0f*cx[c]; ay[c] = -2.0f*cy[c]; az[c] = -2.0f*cz[c];
        bd0[c] = 1e30f; bd1[c] = 1e30f; bd2[c] = 1e30f;
        bi0[c] = 0; bi1[c] = 0; bi2[c] = 0;
    }

    for (int t0 = 0; t0 < NN; t0 += 512) {
        __syncthreads();
        for (int i = tid; i < 512; i += 256) {
            int n = t0 + i;
            st[i] = make_float4(O[n*3], O[n*3+1], O[n*3+2], Q[n]);
        }
        __syncthreads();
        #pragma unroll 2
        for (int i = lane; i < 512; i += 32) {
            float4 pt = st[i];
            int n = t0 + i;
            #pragma unroll
            for (int c = 0; c < 4; c++) {
                float t = pt.w + c2[c];
                t = fmaf(ax[c], pt.x, t); t = fmaf(ay[c], pt.y, t); t = fmaf(az[c], pt.z, t);
                if (t < bd2[c]) {
                    if (t < bd1[c]) {
                        bd2[c] = bd1[c]; bi2[c] = bi1[c];
                        if (t < bd0[c]) { bd1[c] = bd0[c]; bi1[c] = bi0[c]; bd0[c] = t; bi0[c] = n; }
                        else            { bd1[c] = t; bi1[c] = n; }
                    } else { bd2[c] = t; bi2[c] = n; }
                }
            }
        }
    }
    volatile float* mw = mwB + wid*96;
    volatile int*   mi = miB + wid*96;
    #pragma unroll
    for (int c = 0; c < 4; c++)
        merge_write(bd0[c], bd1[c], bd2[c], bi0[c], bi1[c], bi2[c],
                    mw, mi, lane, O, b, mbase + c, cx[c], cy[c], cz[c]);
}

// ---------------- fused mid kernel: gemmG (blocks 0..255) || three_nn (256..767) ----------------
__global__ void __launch_bounds__(256) mid_kernel(const float* __restrict__ feat,
                                                  const float* __restrict__ oxyz)
{
    extern __shared__ char smraw[];
    int bx = blockIdx.x;
    if (bx < 256) gemmG_body(feat, bx, smraw);
    else          three_nn_body(oxyz, bx - 256, smraw);
}

// ---------------- combine: h1T[c][m] = relu(sum_r w_r*G[i_r][c] + rel.W1rel[c] + b1[c]) ----------------
__global__ void combine_kernel(const float* __restrict__ w1, const float* __restrict__ b1)
{
    __shared__ float wr0[128], wr1[128], wr2[128], sb[128];
    __shared__ float tr[128][9];
    int tid = threadIdx.x, lane = tid & 31, wid = tid >> 5;
    if (tid < 128) {
        const float* wrow = w1 + tid*131;
        wr0[tid] = wrow[0]; wr1[tid] = wrow[1]; wr2[tid] = wrow[2];
        sb[tid]  = b1[tid];
    }
    __syncthreads();
    int m = blockIdx.x*8 + wid;                      // global corner 0..16383
    int b = m >> 13, mb = m & 8191;
    size_t base3 = ((size_t)b*M_TOT + mb)*3;
    int i0 = g_nni[base3+0], i1 = g_nni[base3+1], i2 = g_nni[base3+2];
    float w0 = g_nnw[base3+0], w1w = g_nnw[base3+1], w2w = g_nnw[base3+2];
    float rx = g_rel[(size_t)m*3+0], ry = g_rel[(size_t)m*3+1], rz = g_rel[(size_t)m*3+2];
    const float* G0 = g_G + ((size_t)b*NN + i0)*128;
    const float* G1 = g_G + ((size_t)b*NN + i1)*128;
    const float* G2 = g_G + ((size_t)b*NN + i2)*128;
    int c0 = lane*4;
    float4 a = *(const float4*)(G0 + c0);
    float4 bq = *(const float4*)(G1 + c0);
    float4 cq = *(const float4*)(G2 + c0);
    float va[4] = {a.x,a.y,a.z,a.w};
    float vb[4] = {bq.x,bq.y,bq.z,bq.w};
    float vc[4] = {cq.x,cq.y,cq.z,cq.w};
    #pragma unroll
    for (int j = 0; j < 4; j++) {
        int o = c0 + j;
        float acc = w0*va[j] + w1w*vb[j] + w2w*vc[j];
        acc = fmaf(rx, wr0[o], acc);
        acc = fmaf(ry, wr1[o], acc);
        acc = fmaf(rz, wr2[o], acc);
        tr[o][wid] = fmaxf(acc + sb[o], 0.0f);
    }
    __syncthreads();
    // write transposed: h1T[c][m0..m0+7]
    int c = tid >> 1, half = (tid & 1)*4;
    int m0 = blockIdx.x*8;
    float4 v = {tr[c][half+0], tr[c][half+1], tr[c][half+2], tr[c][half+3]};
    *(float4*)&g_h1T[(size_t)c*MG + m0 + half] = v;
}

// ---------------- gemm2 (tf32 tensor-core) + fused relu + maxpool over 64 ----------------
__global__ void __launch_bounds__(256) gemm2_pool_kernel(const float* __restrict__ bias)
{
    __shared__ float As[2][16][132];     // [k][m], padded
    __shared__ float Bs[2][16][68];      // [k][o], padded
    __shared__ int spool[128];           // [2 pool-groups][64 o]
    int m0 = blockIdx.x*128, o0 = blockIdx.y*64;
    int tid = threadIdx.x, lane = tid & 31, wid = tid >> 5;
    int wm = wid >> 1, wn = wid & 1;
    int kr = tid >> 4, c16 = tid & 15;
    if (tid < 128) spool[tid] = 0;

    float acc[2][4][4] = {};

    {
        const float* ap = &g_h1T[(size_t)kr*MG + m0 + c16*8];
        float4 a0 = *(const float4*)ap;
        float4 a1 = *(const float4*)(ap + 4);
        float* d = &As[0][kr][c16*8];
        d[0]=tf32r(a0.x); d[1]=tf32r(a0.y); d[2]=tf32r(a0.z); d[3]=tf32r(a0.w);
        d[4]=tf32r(a1.x); d[5]=tf32r(a1.y); d[6]=tf32r(a1.z); d[7]=tf32r(a1.w);
        float4 bv = *(const float4*)&g_w2T[kr*256 + o0 + c16*4];
        float* e = &Bs[0][kr][c16*4];
        e[0]=tf32r(bv.x); e[1]=tf32r(bv.y); e[2]=tf32r(bv.z); e[3]=tf32r(bv.w);
    }
    __syncthreads();

    int buf = 0;
    int lk = lane & 3, lr = lane >> 2;
    #pragma unroll 1
    for (int kb = 0; kb < 8; kb++) {
        bool has = kb < 7;
        float4 na0, na1, nb;
        if (has) {
            int kk = (kb+1)*16 + kr;
            const float* ap = &g_h1T[(size_t)kk*MG + m0 + c16*8];
            na0 = *(const float4*)ap;
            na1 = *(const float4*)(ap + 4);
            nb  = *(const float4*)&g_w2T[kk*256 + o0 + c16*4];
        }
        #pragma unroll
        for (int ks = 0; ks < 2; ks++) {
            int klo = ks*8 + lk;
            uint32_t afr[2][4];
            #pragma unroll
            for (int mt = 0; mt < 2; mt++) {
                int mr = wm*32 + mt*16 + lr;
                afr[mt][0] = __float_as_uint(As[buf][klo  ][mr]);
                afr[mt][1] = __float_as_uint(As[buf][klo  ][mr+8]);
                afr[mt][2] = __float_as_uint(As[buf][klo+4][mr]);
                afr[mt][3] = __float_as_uint(As[buf][klo+4][mr+8]);
            }
            uint32_t bfr[4][2];
            #pragma unroll
            for (int nt = 0; nt < 4; nt++) {
                int nr = wn*32 + nt*8 + lr;
                bfr[nt][0] = __float_as_uint(Bs[buf][klo  ][nr]);
                bfr[nt][1] = __float_as_uint(Bs[buf][klo+4][nr]);
            }
            #pragma unroll
            for (int mt = 0; mt < 2; mt++)
                #pragma unroll
                for (int nt = 0; nt < 4; nt++)
                    mma_tf32(acc[mt][nt], afr[mt], bfr[nt]);
        }
        if (has) {
            int nbuf = buf^1;
            float* d = &As[nbuf][kr][c16*8];
            d[0]=tf32r(na0.x); d[1]=tf32r(na0.y); d[2]=tf32r(na0.z); d[3]=tf32r(na0.w);
            d[4]=tf32r(na1.x); d[5]=tf32r(na1.y); d[6]=tf32r(na1.z); d[7]=tf32r(na1.w);
            float* e = &Bs[nbuf][kr][c16*4];
            e[0]=tf32r(nb.x); e[1]=tf32r(nb.y); e[2]=tf32r(nb.z); e[3]=tf32r(nb.w);
            __syncthreads();
            buf = nbuf;
        }
    }

    int grp = wm >> 1;
    #pragma unroll
    for (int nt = 0; nt < 4; nt++) {
        int c0 = wn*32 + nt*8 + (lane & 3)*2;
        float b0v = bias[o0 + c0], b1v = bias[o0 + c0 + 1];
        float p0v = 0.0f, p1v = 0.0f;
        #pragma unroll
        for (int mt = 0; mt < 2; mt++) {
            p0v = fmaxf(p0v, acc[mt][nt][0] + b0v);
            p0v = fmaxf(p0v, acc[mt][nt][2] + b0v);
            p1v = fmaxf(p1v, acc[mt][nt][1] + b1v);
            p1v = fmaxf(p1v, acc[mt][nt][3] + b1v);
        }
        atomicMax(&spool[grp*64 + c0],     __float_as_int(p0v));
        atomicMax(&spool[grp*64 + c0 + 1], __float_as_int(p1v));
    }
    __syncthreads();
    if (tid < 128) {
        int g = tid >> 6, ol = tid & 63;
        int b  = m0 >> 13;
        int p0 = (m0 >> 6) & 127;
        g_pool[((size_t)b*256 + o0 + ol)*NPT + p0 + g] = __int_as_float(spool[g*64 + ol]);
    }
}

// ---------------- fused linear + train-mode BN + relu ----------------
__global__ void lin_bn_kernel(const float* __restrict__ W, const float* __restrict__ bias,
                              const float* __restrict__ gam, const float* __restrict__ bet,
                              int stage)
{
    int o = blockIdx.x, tid = threadIdx.x;            // 256 threads = (b,p)
    int b = tid >> 7, p = tid & 127;
    int K = stage ? 128 : 256;
    const float* X = stage ? g_z0 : g_pool;
    __shared__ float ws[256];
    if (tid < K) ws[tid] = W[o*K + tid];
    __syncthreads();
    const float* Xb = X + (size_t)b*K*NPT + p;
    float acc = bias[o];
    #pragma unroll 8
    for (int c = 0; c < K; c++) acc = fmaf(ws[c], Xb[(size_t)c*NPT], acc);
    __shared__ float red[256];
    red[tid] = acc; __syncthreads();
    #pragma unroll
    for (int s = 128; s > 0; s >>= 1) { if (tid < s) red[tid] += red[tid+s]; __syncthreads(); }
    float mean = red[0] * (1.0f/256.0f);
    __syncthreads();
    float d = acc - mean;
    red[tid] = d*d; __syncthreads();
    #pragma unroll
    for (int s = 128; s > 0; s >>= 1) { if (tid < s) red[tid] += red[tid+s]; __syncthreads(); }
    float var = red[0] * (1.0f/256.0f);
    float z = d * rsqrtf(var + 1e-5f) * gam[o] + bet[o];
    float* Y = stage ? g_z1 : g_z0;
    Y[((size_t)b*128 + o)*NPT + p] = fmaxf(z, 0.0f);
}

__global__ void final_kernel(const float* __restrict__ W, const float* __restrict__ bias,
                             float* __restrict__ out)
{
    int b = blockIdx.x, p = threadIdx.x;
    const float* Z = g_z1 + (size_t)b*128*NPT;
    float acc = bias[0];
    #pragma unroll 8
    for (int c = 0; c < 128; c++) acc = fmaf(W[c], Z[(size_t)c*NPT + p], acc);
    out[b*NPT + p] = acc;
}

// ---------------- launch ----------------
extern "C" void kernel_launch(void* const* d_in, const int* in_sizes, int n_in,
                              void* d_out, int out_size)
{
    const float* oxyz  = (const float*)d_in[0];
    const float* ofeat = (const float*)d_in[1];
    const float* cand  = (const float*)d_in[2];
    // d_in[3] = pred_cls (unused)
    const float* poff  = (const float*)d_in[4];
    const float* pacls = (const float*)d_in[5];
    const float* pares = (const float*)d_in[6];
    const float* w1    = (const float*)d_in[7];
    const float* b1    = (const float*)d_in[8];
    const float* w2    = (const float*)d_in[9];
    const float* b2    = (const float*)d_in[10];
    const float* wi0   = (const float*)d_in[11];
    const float* bi0   = (const float*)d_in[12];
    const float* gi0   = (const float*)d_in[13];
    const float* bei0  = (const float*)d_in[14];
    const float* wi1   = (const float*)d_in[15];
    const float* bi1   = (const float*)d_in[16];
    const float* gi1   = (const float*)d_in[17];
    const float* bei1  = (const float*)d_in[18];
    const float* wi2   = (const float*)d_in[19];
    const float* bi2   = (const float*)d_in[20];
    float* out = (float*)d_out;

    setup_kernel<<<320, 256>>>(cand, poff, pacls, pares, oxyz, w1, w2);
    mid_kernel<<<768, 256, 25088>>>(ofeat, oxyz);     // gemmG (256 blocks) || three_nn (512 blocks)
    combine_kernel<<<2048, 256>>>(w1, b1);
    gemm2_pool_kernel<<<dim3(128, 4), 256>>>(b2);
    lin_bn_kernel<<<128, 256>>>(wi0, bi0, gi0, bei0, 0);
    lin_bn_kernel<<<128, 256>>>(wi1, bi1, gi1, bei1, 1);
    final_kernel<<<2, 128>>>(wi2, bi2, out);
}

// round 7
// speedup vs baseline: 1.0688x; 1.0688x over previous
#include <cuda_runtime.h>
#include <math.h>
#include <stdint.h>

#define BS2   2
#define NN    8192
#define NPT   128
#define CC    128
#define M_TOT 8192        // NPT*64 per batch
#define MG    16384       // total corners

// ---------------- device scratch ----------------
static __device__ float g_p2[(size_t)BS2*NN];
static __device__ float g_rel[(size_t)MG*3];
static __device__ float g_cor[(size_t)MG*3];
static __device__ int   g_nni[(size_t)MG*3];
static __device__ float g_nnw[(size_t)MG*3];
static __device__ float g_w1T[128*128];                 // [k][o]
static __device__ float g_w2T[128*256];                 // [k][o]
static __device__ float g_G[(size_t)BS2*NN*128];        // [b][n][o] = W1f . f
static __device__ float g_h1T[(size_t)128*MG];          // [c][m]
static __device__ float g_pool[(size_t)BS2*256*NPT];    // [b][o][p]
static __device__ float g_z0[(size_t)BS2*128*NPT];
static __device__ float g_z1[(size_t)BS2*128*NPT];

__device__ __forceinline__ float tf32r(float x) {
    uint32_t u; asm("cvt.rna.tf32.f32 %0, %1;" : "=r"(u) : "f"(x));
    return __uint_as_float(u);
}

__device__ __forceinline__ void mma_tf32(float c[4], const uint32_t a[4], const uint32_t b[2]) {
    asm volatile(
        "mma.sync.aligned.m16n8k8.row.col.f32.tf32.tf32.f32 "
        "{%0,%1,%2,%3}, {%4,%5,%6,%7}, {%8,%9}, {%0,%1,%2,%3};\n"
        : "+f"(c[0]), "+f"(c[1]), "+f"(c[2]), "+f"(c[3])
        : "r"(a[0]), "r"(a[1]), "r"(a[2]), "r"(a[3]), "r"(b[0]), "r"(b[1]));
}

// ---------------- fused setup: decode + p2 + transpose W1f / W2 ----------------
__global__ void setup_kernel(const float* __restrict__ cand,
                             const float* __restrict__ off,
                             const float* __restrict__ acls,
                             const float* __restrict__ ares,
                             const float* __restrict__ oxyz,
                             const float* __restrict__ w1,
                             const float* __restrict__ w2)
{
    int bx = blockIdx.x, tid = threadIdx.x;
    if (bx < 64) {
        int t = bx*256 + tid;                        // 16384 = b*8192 + p*64 + k
        int k  = t & 63;
        int bp = t >> 6;
        const float* a = acls + bp*12;
        float best = a[0]; int bi = 0;
        #pragma unroll
        for (int j = 1; j < 12; j++) { float v = a[j]; if (v > best) { best = v; bi = j; } }
        float res = ares[bp*12 + bi];
        const float PI_F = 3.14159265358979323846f;
        float ang = (float)bi * (float)(2.0*3.14159265358979323846/12.0) + res;
        float heading = (ang > PI_F) ? (ang - 2.0f*PI_F) : ang;
        float s, c; sincosf(heading, &s, &c);
        const float* o6 = off + bp*6;
        float cx = cand[bp*3+0] + o6[0];
        float cy = cand[bp*3+1] + o6[1];
        float cz = cand[bp*3+2] + o6[2];
        float lx = fmaxf(o6[3]*2.0f, 0.1f);
        float ly = fmaxf(o6[4]*2.0f, 0.1f);
        float lz = fmaxf(o6[5]*2.0f, 0.1f);
        float gv[4] = {-1.0f, -1.0f/3.0f, 1.0f/3.0f, 1.0f};
        float gx = gv[(k>>4)&3] * lx;
        float gy = gv[(k>>2)&3] * ly;
        float gz = gv[k&3]      * lz;
        float rx = gx*c - gy*s;
        float ry = gx*s + gy*c;
        float rz = gz;
        size_t b3 = (size_t)t*3;
        g_rel[b3+0] = rx; g_rel[b3+1] = ry; g_rel[b3+2] = rz;
        g_cor[b3+0] = rx + cx; g_cor[b3+1] = ry + cy; g_cor[b3+2] = rz + cz;
    } else if (bx < 128) {
        int t = (bx-64)*256 + tid;
        float x = oxyz[t*3], y = oxyz[t*3+1], z = oxyz[t*3+2];
        g_p2[t] = x*x + y*y + z*z;
    } else if (bx < 192) {
        int t = (bx-128)*256 + tid;                  // 16384 = k*128+o
        int o = t & 127, k = t >> 7;
        g_w1T[t] = w1[o*131 + 3 + k];
    } else {
        int t = (bx-192)*256 + tid;                  // 32768 = k*256+o
        int o = t & 255, k = t >> 8;
        g_w2T[t] = w2[o*128 + k];
    }
}

// ---------------- top-3 merge helper ----------------
__device__ __forceinline__ void merge_write(float d0, float d1, float d2,
                                            int i0, int i1, int i2,
                                            volatile float* mw, volatile int* mi,
                                            int lane, const float* __restrict__ O,
                                            int b, int m, float cx, float cy, float cz)
{
    mw[lane*3+0] = d0; mi[lane*3+0] = i0;
    mw[lane*3+1] = d1; mi[lane*3+1] = i1;
    mw[lane*3+2] = d2; mi[lane*3+2] = i2;
    __syncwarp();
    int win[3];
    #pragma unroll
    for (int r = 0; r < 3; r++) {
        float v = 1e30f; int pos = 1<<30;
        #pragma unroll
        for (int j = 0; j < 3; j++) {
            int jj = lane + 32*j;
            float vv = mw[jj];
            if (vv < v || (vv == v && jj < pos)) { v = vv; pos = jj; }
        }
        #pragma unroll
        for (int offi = 16; offi; offi >>= 1) {
            float v2 = __shfl_xor_sync(0xffffffffu, v, offi);
            int   q2 = __shfl_xor_sync(0xffffffffu, pos, offi);
            if (v2 < v || (v2 == v && q2 < pos)) { v = v2; pos = q2; }
        }
        win[r] = mi[pos];
        if (lane == 0) mw[pos] = 2e30f;
        __syncwarp();
    }
    if (lane == 0) {
        float w[3], ssum = 0.0f;
        #pragma unroll
        for (int r = 0; r < 3; r++) {
            const float* P = O + (size_t)win[r]*3;
            float dx = P[0]-cx, dy = P[1]-cy, dz = P[2]-cz;
            float d = sqrtf(dx*dx + dy*dy + dz*dz);
            w[r] = 1.0f / (d + 1e-8f);
            ssum += w[r];
        }
        size_t base = ((size_t)b*M_TOT + m)*3;
        float inv = 1.0f/ssum;
        #pragma unroll
        for (int r = 0; r < 3; r++) { g_nni[base+r] = win[r]; g_nnw[base+r] = w[r]*inv; }
    }
    __syncwarp();
}

// ---------------- gemmG body (R3-proven config; dynamic smem) ----------------
__device__ __forceinline__ void gemmG_body(const float* __restrict__ feat, int bx, char* smraw)
{
    float* NsB = (float*)smraw;                  // [2][16][132]
    float* OsB = (float*)(smraw + 16896);        // [2][16][64]
    #define NS(bu,k,i) NsB[(((bu)*16)+(k))*132+(i)]
    #define OS(bu,k,i) OsB[(((bu)*16)+(k))*64+(i)]
    int nt = bx & 63, rest = bx >> 6;
    int ot = rest & 1, b = rest >> 1;
    int n0 = nt*128, o0 = ot*64;
    int tid = threadIdx.x;
    int kr  = tid >> 4;
    int nc  = (tid & 15)*8;
    int oc  = (tid & 15)*4;
    int tr  = (tid >> 4)*8;
    int tc  = (tid & 15)*4;
    const float* F = feat + (size_t)b*CC*NN;

    float acc[8][4] = {};
    float4 na0, na1, nb;
    na0 = *(const float4*)&F[(size_t)kr*NN + n0 + nc];
    na1 = *(const float4*)&F[(size_t)kr*NN + n0 + nc + 4];
    nb  = *(const float4*)&g_w1T[kr*128 + o0 + oc];
    *(float4*)&NS(0,kr,nc)   = na0;
    *(float4*)&NS(0,kr,nc+4) = na1;
    *(float4*)&OS(0,kr,oc)   = nb;
    __syncthreads();
    int buf = 0;
    #pragma unroll 1
    for (int kb = 0; kb < 8; kb++) {
        bool has = kb < 7;
        if (has) {
            int kk = (kb+1)*16 + kr;
            na0 = *(const float4*)&F[(size_t)kk*NN + n0 + nc];
            na1 = *(const float4*)&F[(size_t)kk*NN + n0 + nc + 4];
            nb  = *(const float4*)&g_w1T[kk*128 + o0 + oc];
        }
        #pragma unroll
        for (int k = 0; k < 16; k++) {
            float4 a0 = *(const float4*)&NS(buf,k,tr);
            float4 a1 = *(const float4*)&NS(buf,k,tr+4);
            float4 bq = *(const float4*)&OS(buf,k,tc);
            float ar[8] = {a0.x,a0.y,a0.z,a0.w,a1.x,a1.y,a1.z,a1.w};
            float br[4] = {bq.x,bq.y,bq.z,bq.w};
            #pragma unroll
            for (int i = 0; i < 8; i++)
                #pragma unroll
                for (int j = 0; j < 4; j++)
                    acc[i][j] = fmaf(ar[i], br[j], acc[i][j]);
        }
        if (has) {
            int nbuf = buf^1;
            *(float4*)&NS(nbuf,kr,nc)   = na0;
            *(float4*)&NS(nbuf,kr,nc+4) = na1;
            *(float4*)&OS(nbuf,kr,oc)   = nb;
            __syncthreads();
            buf = nbuf;
        }
    }
    float* Gp = g_G + ((size_t)b*NN + n0 + tr)*128 + o0 + tc;
    #pragma unroll
    for (int i = 0; i < 8; i++) {
        float4 v = {acc[i][0], acc[i][1], acc[i][2], acc[i][3]};
        *(float4*)(Gp + (size_t)i*128) = v;
    }
    #undef NS
    #undef OS
}

// ---------------- three_nn body: warp handles 2 corners (R5-proven; dynamic smem) ----------------
__device__ __forceinline__ void three_nn_body(const float* __restrict__ oxyz, int bx, char* smraw)
{
    float4* st  = (float4*)smraw;                 // 512*16 = 8192
    float*  mwB = (float*)(smraw + 8192);         // 8*96*4
    int*    miB = (int*)(smraw + 8192 + 3072);    // 8*96*4
    int tid = threadIdx.x, lane = tid & 31, wid = tid >> 5;
    int gw = bx*8 + wid;                          // 0..8191
    int b  = gw >> 12;
    int mA = (gw & 4095) * 2;
    int mB = mA + 1;
    const float* O = oxyz + (size_t)b*NN*3;
    const float* Q = g_p2 + (size_t)b*NN;

    size_t bA = ((size_t)b*M_TOT + mA)*3;
    size_t bB = ((size_t)b*M_TOT + mB)*3;
    float cxA = g_cor[bA+0], cyA = g_cor[bA+1], czA = g_cor[bA+2];
    float cxB = g_cor[bB+0], cyB = g_cor[bB+1], czB = g_cor[bB+2];
    float c2A = cxA*cxA + cyA*cyA + czA*czA;
    float c2B = cxB*cxB + cyB*cyB + czB*czB;
    float axA = -2.0f*cxA, ayA = -2.0f*cyA, azA = -2.0f*czA;
    float axB = -2.0f*cxB, ayB = -2.0f*cyB, azB = -2.0f*czB;

    float dA0 = 1e30f, dA1 = 1e30f, dA2 = 1e30f; int iA0 = 0, iA1 = 0, iA2 = 0;
    float dB0 = 1e30f, dB1 = 1e30f, dB2 = 1e30f; int iB0 = 0, iB1 = 0, iB2 = 0;

    for (int t0 = 0; t0 < NN; t0 += 512) {
        __syncthreads();
        for (int i = tid; i < 512; i += 256) {
            int n = t0 + i;
            st[i] = make_float4(O[n*3], O[n*3+1], O[n*3+2], Q[n]);
        }
        __syncthreads();
        #pragma unroll 4
        for (int i = lane; i < 512; i += 32) {
            float4 pt = st[i];
            int n = t0 + i;
            float t = pt.w + c2A;
            t = fmaf(axA, pt.x, t); t = fmaf(ayA, pt.y, t); t = fmaf(azA, pt.z, t);
            if (t < dA2) {
                if (t < dA1) {
                    dA2 = dA1; iA2 = iA1;
                    if (t < dA0) { dA1 = dA0; iA1 = iA0; dA0 = t; iA0 = n; }
                    else         { dA1 = t;  iA1 = n; }
                } else { dA2 = t; iA2 = n; }
            }
            float u = pt.w + c2B;
            u = fmaf(axB, pt.x, u); u = fmaf(ayB, pt.y, u); u = fmaf(azB, pt.z, u);
            if (u < dB2) {
                if (u < dB1) {
                    dB2 = dB1; iB2 = iB1;
                    if (u < dB0) { dB1 = dB0; iB1 = iB0; dB0 = u; iB0 = n; }
                    else         { dB1 = u;  iB1 = n; }
                } else { dB2 = u; iB2 = n; }
            }
        }
    }
    volatile float* mw = mwB + wid*96;
    volatile int*   mi = miB + wid*96;
    merge_write(dA0, dA1, dA2, iA0, iA1, iA2, mw, mi, lane, O, b, mA, cxA, cyA, czA);
    merge_write(dB0, dB1, dB2, iB0, iB1, iB2, mw, mi, lane, O, b, mB, cxB, cyB, czB);
}

// ---------------- fused mid kernel: 1280 blocks; every 5th = gemmG, rest = three_nn ----------------
__global__ void __launch_bounds__(256) mid_kernel(const float* __restrict__ feat,
                                                  const float* __restrict__ oxyz)
{
    extern __shared__ char smraw[];
    int bx = blockIdx.x;
    if (bx % 5 == 0) gemmG_body(feat, bx/5, smraw);           // 256 gemmG blocks
    else             three_nn_body(oxyz, bx - 1 - bx/5, smraw); // 1024 three_nn blocks
}

// ---------------- combine v2: block = 32 corners, coalesced h1T row writes ----------------
__global__ void __launch_bounds__(256) combine_kernel(const float* __restrict__ w1,
                                                      const float* __restrict__ b1)
{
    __shared__ float wr0[128], wr1[128], wr2[128], sb[128];
    __shared__ float tr[128][33];
    int tid = threadIdx.x, lane = tid & 31, wid = tid >> 5;
    if (tid < 128) {
        const float* wrow = w1 + tid*131;
        wr0[tid] = wrow[0]; wr1[tid] = wrow[1]; wr2[tid] = wrow[2];
        sb[tid]  = b1[tid];
    }
    __syncthreads();
    int m0 = blockIdx.x*32;
    #pragma unroll 1
    for (int cc = 0; cc < 4; cc++) {
        int ml = wid*4 + cc;                         // 0..31 local corner
        int m  = m0 + ml;
        int b = m >> 13, mb = m & 8191;
        size_t base3 = ((size_t)b*M_TOT + mb)*3;
        int i0 = g_nni[base3+0], i1 = g_nni[base3+1], i2 = g_nni[base3+2];
        float w0 = g_nnw[base3+0], w1w = g_nnw[base3+1], w2w = g_nnw[base3+2];
        float rx = g_rel[(size_t)m*3+0], ry = g_rel[(size_t)m*3+1], rz = g_rel[(size_t)m*3+2];
        const float* G0 = g_G + ((size_t)b*NN + i0)*128;
        const float* G1 = g_G + ((size_t)b*NN + i1)*128;
        const float* G2 = g_G + ((size_t)b*NN + i2)*128;
        int c0 = lane*4;
        float4 a  = *(const float4*)(G0 + c0);
        float4 bq = *(const float4*)(G1 + c0);
        float4 cq = *(const float4*)(G2 + c0);
        float va[4] = {a.x,a.y,a.z,a.w};
        float vb[4] = {bq.x,bq.y,bq.z,bq.w};
        float vc[4] = {cq.x,cq.y,cq.z,cq.w};
        #pragma unroll
        for (int j = 0; j < 4; j++) {
            int o = c0 + j;
            float acc = w0*va[j] + w1w*vb[j] + w2w*vc[j];
            acc = fmaf(rx, wr0[o], acc);
            acc = fmaf(ry, wr1[o], acc);
            acc = fmaf(rz, wr2[o], acc);
            tr[o][ml] = fmaxf(acc + sb[o], 0.0f);
        }
    }
    __syncthreads();
    // write h1T rows: 128 rows x 32 floats, 128B per row, coalesced
    int c = tid >> 1, base = (tid & 1)*16;
    float* dst = &g_h1T[(size_t)c*MG + m0 + base];
    #pragma unroll
    for (int q = 0; q < 4; q++) {
        float4 v = {tr[c][base+q*4+0], tr[c][base+q*4+1], tr[c][base+q*4+2], tr[c][base+q*4+3]};
        *(float4*)(dst + q*4) = v;
    }
}

// ---------------- gemm2 (tf32 tensor-core) + fused relu + maxpool over 64 ----------------
__global__ void __launch_bounds__(256) gemm2_pool_kernel(const float* __restrict__ bias)
{
    __shared__ float As[2][16][132];     // [k][m], padded
    __shared__ float Bs[2][16][68];      // [k][o], padded
    __shared__ int spool[128];           // [2 pool-groups][64 o]
    int m0 = blockIdx.x*128, o0 = blockIdx.y*64;
    int tid = threadIdx.x, lane = tid & 31, wid = tid >> 5;
    int wm = wid >> 1, wn = wid & 1;
    int kr = tid >> 4, c16 = tid & 15;
    if (tid < 128) spool[tid] = 0;

    float acc[2][4][4] = {};

    {
        const float* ap = &g_h1T[(size_t)kr*MG + m0 + c16*8];
        float4 a0 = *(const float4*)ap;
        float4 a1 = *(const float4*)(ap + 4);
        float* d = &As[0][kr][c16*8];
        d[0]=tf32r(a0.x); d[1]=tf32r(a0.y); d[2]=tf32r(a0.z); d[3]=tf32r(a0.w);
        d[4]=tf32r(a1.x); d[5]=tf32r(a1.y); d[6]=tf32r(a1.z); d[7]=tf32r(a1.w);
        float4 bv = *(const float4*)&g_w2T[kr*256 + o0 + c16*4];
        float* e = &Bs[0][kr][c16*4];
        e[0]=tf32r(bv.x); e[1]=tf32r(bv.y); e[2]=tf32r(bv.z); e[3]=tf32r(bv.w);
    }
    __syncthreads();

    int buf = 0;
    int lk = lane & 3, lr = lane >> 2;
    #pragma unroll 1
    for (int kb = 0; kb < 8; kb++) {
        bool has = kb < 7;
        float4 na0, na1, nb;
        if (has) {
            int kk = (kb+1)*16 + kr;
            const float* ap = &g_h1T[(size_t)kk*MG + m0 + c16*8];
            na0 = *(const float4*)ap;
            na1 = *(const float4*)(ap + 4);
            nb  = *(const float4*)&g_w2T[kk*256 + o0 + c16*4];
        }
        #pragma unroll
        for (int ks = 0; ks < 2; ks++) {
            int klo = ks*8 + lk;
            uint32_t afr[2][4];
            #pragma unroll
            for (int mt = 0; mt < 2; mt++) {
                int mr = wm*32 + mt*16 + lr;
                afr[mt][0] = __float_as_uint(As[buf][klo  ][mr]);
                afr[mt][1] = __float_as_uint(As[buf][klo  ][mr+8]);
                afr[mt][2] = __float_as_uint(As[buf][klo+4][mr]);
                afr[mt][3] = __float_as_uint(As[buf][klo+4][mr+8]);
            }
            uint32_t bfr[4][2];
            #pragma unroll
            for (int nt = 0; nt < 4; nt++) {
                int nr = wn*32 + nt*8 + lr;
                bfr[nt][0] = __float_as_uint(Bs[buf][klo  ][nr]);
                bfr[nt][1] = __float_as_uint(Bs[buf][klo+4][nr]);
            }
            #pragma unroll
            for (int mt = 0; mt < 2; mt++)
                #pragma unroll
                for (int nt = 0; nt < 4; nt++)
                    mma_tf32(acc[mt][nt], afr[mt], bfr[nt]);
        }
        if (has) {
            int nbuf = buf^1;
            float* d = &As[nbuf][kr][c16*8];
            d[0]=tf32r(na0.x); d[1]=tf32r(na0.y); d[2]=tf32r(na0.z); d[3]=tf32r(na0.w);
            d[4]=tf32r(na1.x); d[5]=tf32r(na1.y); d[6]=tf32r(na1.z); d[7]=tf32r(na1.w);
            float* e = &Bs[nbuf][kr][c16*4];
            e[0]=tf32r(nb.x); e[1]=tf32r(nb.y); e[2]=tf32r(nb.z); e[3]=tf32r(nb.w);
            __syncthreads();
            buf = nbuf;
        }
    }

    int grp = wm >> 1;
    #pragma unroll
    for (int nt = 0; nt < 4; nt++) {
        int c0 = wn*32 + nt*8 + (lane & 3)*2;
        float b0v = bias[o0 + c0], b1v = bias[o0 + c0 + 1];
        float p0v = 0.0f, p1v = 0.0f;
        #pragma unroll
        for (int mt = 0; mt < 2; mt++) {
            p0v = fmaxf(p0v, acc[mt][nt][0] + b0v);
            p0v = fmaxf(p0v, acc[mt][nt][2] + b0v);
            p1v = fmaxf(p1v, acc[mt][nt][1] + b1v);
            p1v = fmaxf(p1v, acc[mt][nt][3] + b1v);
        }
        atomicMax(&spool[grp*64 + c0],     __float_as_int(p0v));
        atomicMax(&spool[grp*64 + c0 + 1], __float_as_int(p1v));
    }
    __syncthreads();
    if (tid < 128) {
        int g = tid >> 6, ol = tid & 63;
        int b  = m0 >> 13;
        int p0 = (m0 >> 6) & 127;
        g_pool[((size_t)b*256 + o0 + ol)*NPT + p0 + g] = __int_as_float(spool[g*64 + ol]);
    }
}

// ---------------- fused linear + train-mode BN + relu ----------------
__global__ void lin_bn_kernel(const float* __restrict__ W, const float* __restrict__ bias,
                              const float* __restrict__ gam, const float* __restrict__ bet,
                              int stage)
{
    int o = blockIdx.x, tid = threadIdx.x;            // 256 threads = (b,p)
    int b = tid >> 7, p = tid & 127;
    int K = stage ? 128 : 256;
    const float* X = stage ? g_z0 : g_pool;
    __shared__ float ws[256];
    if (tid < K) ws[tid] = W[o*K + tid];
    __syncthreads();
    const float* Xb = X + (size_t)b*K*NPT + p;
    float acc = bias[o];
    #pragma unroll 8
    for (int c = 0; c < K; c++) acc = fmaf(ws[c], Xb[(size_t)c*NPT], acc);
    __shared__ float red[256];
    red[tid] = acc; __syncthreads();
    #pragma unroll
    for (int s = 128; s > 0; s >>= 1) { if (tid < s) red[tid] += red[tid+s]; __syncthreads(); }
    float mean = red[0] * (1.0f/256.0f);
    __syncthreads();
    float d = acc - mean;
    red[tid] = d*d; __syncthreads();
    #pragma unroll
    for (int s = 128; s > 0; s >>= 1) { if (tid < s) red[tid] += red[tid+s]; __syncthreads(); }
    float var = red[0] * (1.0f/256.0f);
    float z = d * rsqrtf(var + 1e-5f) * gam[o] + bet[o];
    float* Y = stage ? g_z1 : g_z0;
    Y[((size_t)b*128 + o)*NPT + p] = fmaxf(z, 0.0f);
}

__global__ void final_kernel(const float* __restrict__ W, const float* __restrict__ bias,
                             float* __restrict__ out)
{
    int b = blockIdx.x, p = threadIdx.x;
    const float* Z = g_z1 + (size_t)b*128*NPT;
    float acc = bias[0];
    #pragma unroll 8
    for (int c = 0; c < 128; c++) acc = fmaf(W[c], Z[(size_t)c*NPT + p], acc);
    out[b*NPT + p] = acc;
}

// ---------------- launch ----------------
extern "C" void kernel_launch(void* const* d_in, const int* in_sizes, int n_in,
                              void* d_out, int out_size)
{
    const float* oxyz  = (const float*)d_in[0];
    const float* ofeat = (const float*)d_in[1];
    const float* cand  = (const float*)d_in[2];
    // d_in[3] = pred_cls (unused)
    const float* poff  = (const float*)d_in[4];
    const float* pacls = (const float*)d_in[5];
    const float* pares = (const float*)d_in[6];
    const float* w1    = (const float*)d_in[7];
    const float* b1    = (const float*)d_in[8];
    const float* w2    = (const float*)d_in[9];
    const float* b2    = (const float*)d_in[10];
    const float* wi0   = (const float*)d_in[11];
    const float* bi0   = (const float*)d_in[12];
    const float* gi0   = (const float*)d_in[13];
    const float* bei0  = (const float*)d_in[14];
    const float* wi1   = (const float*)d_in[15];
    const float* bi1   = (const float*)d_in[16];
    const float* gi1   = (const float*)d_in[17];
    const float* bei1  = (const float*)d_in[18];
    const float* wi2   = (const float*)d_in[19];
    const float* bi2   = (const float*)d_in[20];
    float* out = (float*)d_out;

    setup_kernel<<<320, 256>>>(cand, poff, pacls, pares, oxyz, w1, w2);
    mid_kernel<<<1280, 256, 25088>>>(ofeat, oxyz);    // gemmG (256) interleaved with three_nn (1024)
    combine_kernel<<<512, 256>>>(w1, b1);
    gemm2_pool_kernel<<<dim3(128, 4), 256>>>(b2);
    lin_bn_kernel<<<128, 256>>>(wi0, bi0, gi0, bei0, 0);
    lin_bn_kernel<<<128, 256>>>(wi1, bi1, gi1, bei1, 1);
    final_kernel<<<2, 128>>>(wi2, bi2, out);
}

// round 8
// speedup vs baseline: 1.3412x; 1.2548x over previous
#include <cuda_runtime.h>
#include <math.h>
#include <stdint.h>

#define BS2   2
#define NN    8192
#define NPT   128
#define CC    128
#define M_TOT 8192        // NPT*64 per batch
#define MG    16384       // total corners

// ---------------- device scratch ----------------
static __device__ float g_p2[(size_t)BS2*NN];
static __device__ float g_rel[(size_t)MG*3];
static __device__ float g_cor[(size_t)MG*3];
static __device__ int   g_nni[(size_t)MG*3];
static __device__ float g_nnw[(size_t)MG*3];
static __device__ float g_w1T[128*128];                 // [k][o]
static __device__ float g_w2T[128*256];                 // [k][o]
static __device__ float g_G[(size_t)BS2*NN*128];        // [b][n][o] = W1f . f
static __device__ float g_h1T[(size_t)128*MG];          // [c][m]
static __device__ float g_pool[(size_t)BS2*256*NPT];    // [b][o][p]
static __device__ float g_z0[(size_t)BS2*128*NPT];
static __device__ float g_z1[(size_t)BS2*128*NPT];

__device__ __forceinline__ float tf32r(float x) {
    uint32_t u; asm("cvt.rna.tf32.f32 %0, %1;" : "=r"(u) : "f"(x));
    return __uint_as_float(u);
}

__device__ __forceinline__ void mma_tf32(float c[4], const uint32_t a[4], const uint32_t b[2]) {
    asm volatile(
        "mma.sync.aligned.m16n8k8.row.col.f32.tf32.tf32.f32 "
        "{%0,%1,%2,%3}, {%4,%5,%6,%7}, {%8,%9}, {%0,%1,%2,%3};\n"
        : "+f"(c[0]), "+f"(c[1]), "+f"(c[2]), "+f"(c[3])
        : "r"(a[0]), "r"(a[1]), "r"(a[2]), "r"(a[3]), "r"(b[0]), "r"(b[1]));
}

// ---------------- fused setup: decode + p2 + transpose W1f / W2 ----------------
__global__ void setup_kernel(const float* __restrict__ cand,
                             const float* __restrict__ off,
                             const float* __restrict__ acls,
                             const float* __restrict__ ares,
                             const float* __restrict__ oxyz,
                             const float* __restrict__ w1,
                             const float* __restrict__ w2)
{
    int bx = blockIdx.x, tid = threadIdx.x;
    if (bx < 64) {
        int t = bx*256 + tid;                        // 16384 = b*8192 + p*64 + k
        int k  = t & 63;
        int bp = t >> 6;
        const float* a = acls + bp*12;
        float best = a[0]; int bi = 0;
        #pragma unroll
        for (int j = 1; j < 12; j++) { float v = a[j]; if (v > best) { best = v; bi = j; } }
        float res = ares[bp*12 + bi];
        const float PI_F = 3.14159265358979323846f;
        float ang = (float)bi * (float)(2.0*3.14159265358979323846/12.0) + res;
        float heading = (ang > PI_F) ? (ang - 2.0f*PI_F) : ang;
        float s, c; sincosf(heading, &s, &c);
        const float* o6 = off + bp*6;
        float cx = cand[bp*3+0] + o6[0];
        float cy = cand[bp*3+1] + o6[1];
        float cz = cand[bp*3+2] + o6[2];
        float lx = fmaxf(o6[3]*2.0f, 0.1f);
        float ly = fmaxf(o6[4]*2.0f, 0.1f);
        float lz = fmaxf(o6[5]*2.0f, 0.1f);
        float gv[4] = {-1.0f, -1.0f/3.0f, 1.0f/3.0f, 1.0f};
        float gx = gv[(k>>4)&3] * lx;
        float gy = gv[(k>>2)&3] * ly;
        float gz = gv[k&3]      * lz;
        float rx = gx*c - gy*s;
        float ry = gx*s + gy*c;
        float rz = gz;
        size_t b3 = (size_t)t*3;
        g_rel[b3+0] = rx; g_rel[b3+1] = ry; g_rel[b3+2] = rz;
        g_cor[b3+0] = rx + cx; g_cor[b3+1] = ry + cy; g_cor[b3+2] = rz + cz;
    } else if (bx < 128) {
        int t = (bx-64)*256 + tid;
        float x = oxyz[t*3], y = oxyz[t*3+1], z = oxyz[t*3+2];
        g_p2[t] = x*x + y*y + z*z;
    } else if (bx < 192) {
        int t = (bx-128)*256 + tid;                  // 16384 = k*128+o
        int o = t & 127, k = t >> 7;
        g_w1T[t] = w1[o*131 + 3 + k];
    } else {
        int t = (bx-192)*256 + tid;                  // 32768 = k*256+o
        int o = t & 255, k = t >> 8;
        g_w2T[t] = w2[o*128 + k];
    }
}

// ---------------- gemm_G: G[b][n][o] = sum_c f[b][c][n] * w1T[c][o] ----------------
// tile 128n x 64o, BK=16, micro 8x4, double-buffered (R3/R5-proven).
__global__ void __launch_bounds__(256) gemmG_kernel(const float* __restrict__ feat)
{
    __shared__ float Ns[2][16][132];
    __shared__ float Os[2][16][64];
    int n0 = blockIdx.x*128, o0 = blockIdx.y*64, b = blockIdx.z;
    int tid = threadIdx.x;
    int kr  = tid >> 4;                  // 0..15
    int nc  = (tid & 15)*8;              // A cols (n)
    int oc  = (tid & 15)*4;              // B cols (o)
    int tr  = (tid >> 4)*8;              // micro rows (n)
    int tc  = (tid & 15)*4;              // micro cols (o)
    const float* F = feat + (size_t)b*CC*NN;

    float acc[8][4] = {};
    float4 na0, na1, nb;
    na0 = *(const float4*)&F[(size_t)kr*NN + n0 + nc];
    na1 = *(const float4*)&F[(size_t)kr*NN + n0 + nc + 4];
    nb  = *(const float4*)&g_w1T[kr*128 + o0 + oc];
    *(float4*)&Ns[0][kr][nc]   = na0;
    *(float4*)&Ns[0][kr][nc+4] = na1;
    *(float4*)&Os[0][kr][oc]   = nb;
    __syncthreads();
    int buf = 0;
    #pragma unroll 1
    for (int kb = 0; kb < 8; kb++) {
        bool has = kb < 7;
        if (has) {
            int kk = (kb+1)*16 + kr;
            na0 = *(const float4*)&F[(size_t)kk*NN + n0 + nc];
            na1 = *(const float4*)&F[(size_t)kk*NN + n0 + nc + 4];
            nb  = *(const float4*)&g_w1T[kk*128 + o0 + oc];
        }
        #pragma unroll
        for (int k = 0; k < 16; k++) {
            float4 a0 = *(const float4*)&Ns[buf][k][tr];
            float4 a1 = *(const float4*)&Ns[buf][k][tr+4];
            float4 bq = *(const float4*)&Os[buf][k][tc];
            float ar[8] = {a0.x,a0.y,a0.z,a0.w,a1.x,a1.y,a1.z,a1.w};
            float br[4] = {bq.x,bq.y,bq.z,bq.w};
            #pragma unroll
            for (int i = 0; i < 8; i++)
                #pragma unroll
                for (int j = 0; j < 4; j++)
                    acc[i][j] = fmaf(ar[i], br[j], acc[i][j]);
        }
        if (has) {
            int nbuf = buf^1;
            *(float4*)&Ns[nbuf][kr][nc]   = na0;
            *(float4*)&Ns[nbuf][kr][nc+4] = na1;
            *(float4*)&Os[nbuf][kr][oc]   = nb;
            __syncthreads();
            buf = nbuf;
        }
    }
    float* Gp = g_G + ((size_t)b*NN + n0 + tr)*128 + o0 + tc;
    #pragma unroll
    for (int i = 0; i < 8; i++) {
        float4 v = {acc[i][0], acc[i][1], acc[i][2], acc[i][3]};
        *(float4*)(Gp + (size_t)i*128) = v;
    }
}

// ---------------- top-3 merge helper ----------------
__device__ __forceinline__ void merge_write(float d0, float d1, float d2,
                                            int i0, int i1, int i2,
                                            volatile float* mw, volatile int* mi,
                                            int lane, const float* __restrict__ O,
                                            int b, int m, float cx, float cy, float cz)
{
    mw[lane*3+0] = d0; mi[lane*3+0] = i0;
    mw[lane*3+1] = d1; mi[lane*3+1] = i1;
    mw[lane*3+2] = d2; mi[lane*3+2] = i2;
    __syncwarp();
    int win[3];
    #pragma unroll
    for (int r = 0; r < 3; r++) {
        float v = 1e30f; int pos = 1<<30;
        #pragma unroll
        for (int j = 0; j < 3; j++) {
            int jj = lane + 32*j;
            float vv = mw[jj];
            if (vv < v || (vv == v && jj < pos)) { v = vv; pos = jj; }
        }
        #pragma unroll
        for (int offi = 16; offi; offi >>= 1) {
            float v2 = __shfl_xor_sync(0xffffffffu, v, offi);
            int   q2 = __shfl_xor_sync(0xffffffffu, pos, offi);
            if (v2 < v || (v2 == v && q2 < pos)) { v = v2; pos = q2; }
        }
        win[r] = mi[pos];
        if (lane == 0) mw[pos] = 2e30f;
        __syncwarp();
    }
    if (lane == 0) {
        float w[3], ssum = 0.0f;
        #pragma unroll
        for (int r = 0; r < 3; r++) {
            const float* P = O + (size_t)win[r]*3;
            float dx = P[0]-cx, dy = P[1]-cy, dz = P[2]-cz;
            float d = sqrtf(dx*dx + dy*dy + dz*dz);
            w[r] = 1.0f / (d + 1e-8f);
            ssum += w[r];
        }
        size_t base = ((size_t)b*M_TOT + m)*3;
        float inv = 1.0f/ssum;
        #pragma unroll
        for (int r = 0; r < 3; r++) { g_nni[base+r] = win[r]; g_nnw[base+r] = w[r]*inv; }
    }
    __syncwarp();
}

// ---------------- three_nn: warp handles 2 corners (R5-proven) ----------------
__global__ void three_nn_kernel(const float* __restrict__ oxyz)
{
    __shared__ float4 st[512];
    __shared__ float  mw[8][96];
    __shared__ int    mi[8][96];
    int tid = threadIdx.x, lane = tid & 31, wid = tid >> 5;
    int gw = blockIdx.x*8 + wid;                     // 0..8191
    int b  = gw >> 12;
    int mA = (gw & 4095) * 2;
    int mB = mA + 1;
    const float* O = oxyz + (size_t)b*NN*3;
    const float* Q = g_p2 + (size_t)b*NN;

    size_t bA = ((size_t)b*M_TOT + mA)*3;
    size_t bB = ((size_t)b*M_TOT + mB)*3;
    float cxA = g_cor[bA+0], cyA = g_cor[bA+1], czA = g_cor[bA+2];
    float cxB = g_cor[bB+0], cyB = g_cor[bB+1], czB = g_cor[bB+2];
    float c2A = cxA*cxA + cyA*cyA + czA*czA;
    float c2B = cxB*cxB + cyB*cyB + czB*czB;
    float axA = -2.0f*cxA, ayA = -2.0f*cyA, azA = -2.0f*czA;
    float axB = -2.0f*cxB, ayB = -2.0f*cyB, azB = -2.0f*czB;

    float dA0 = 1e30f, dA1 = 1e30f, dA2 = 1e30f; int iA0 = 0, iA1 = 0, iA2 = 0;
    float dB0 = 1e30f, dB1 = 1e30f, dB2 = 1e30f; int iB0 = 0, iB1 = 0, iB2 = 0;

    for (int t0 = 0; t0 < NN; t0 += 512) {
        __syncthreads();
        for (int i = tid; i < 512; i += 256) {
            int n = t0 + i;
            st[i] = make_float4(O[n*3], O[n*3+1], O[n*3+2], Q[n]);
        }
        __syncthreads();
        #pragma unroll 4
        for (int i = lane; i < 512; i += 32) {
            float4 pt = st[i];
            int n = t0 + i;
            float t = pt.w + c2A;
            t = fmaf(axA, pt.x, t); t = fmaf(ayA, pt.y, t); t = fmaf(azA, pt.z, t);
            if (t < dA2) {
                if (t < dA1) {
                    dA2 = dA1; iA2 = iA1;
                    if (t < dA0) { dA1 = dA0; iA1 = iA0; dA0 = t; iA0 = n; }
                    else         { dA1 = t;  iA1 = n; }
                } else { dA2 = t; iA2 = n; }
            }
            float u = pt.w + c2B;
            u = fmaf(axB, pt.x, u); u = fmaf(ayB, pt.y, u); u = fmaf(azB, pt.z, u);
            if (u < dB2) {
                if (u < dB1) {
                    dB2 = dB1; iB2 = iB1;
                    if (u < dB0) { dB1 = dB0; iB1 = iB0; dB0 = u; iB0 = n; }
                    else         { dB1 = u;  iB1 = n; }
                } else { dB2 = u; iB2 = n; }
            }
        }
    }
    merge_write(dA0, dA1, dA2, iA0, iA1, iA2, mw[wid], mi[wid], lane, O, b, mA, cxA, cyA, czA);
    merge_write(dB0, dB1, dB2, iB0, iB1, iB2, mw[wid], mi[wid], lane, O, b, mB, cxB, cyB, czB);
}

// ---------------- combine v2: block = 32 corners, coalesced h1T row writes ----------------
__global__ void __launch_bounds__(256) combine_kernel(const float* __restrict__ w1,
                                                      const float* __restrict__ b1)
{
    __shared__ float wr0[128], wr1[128], wr2[128], sb[128];
    __shared__ float tr[128][33];
    int tid = threadIdx.x, lane = tid & 31, wid = tid >> 5;
    if (tid < 128) {
        const float* wrow = w1 + tid*131;
        wr0[tid] = wrow[0]; wr1[tid] = wrow[1]; wr2[tid] = wrow[2];
        sb[tid]  = b1[tid];
    }
    __syncthreads();
    int m0 = blockIdx.x*32;
    #pragma unroll 1
    for (int cc = 0; cc < 4; cc++) {
        int ml = wid*4 + cc;                         // 0..31 local corner
        int m  = m0 + ml;
        int b = m >> 13, mb = m & 8191;
        size_t base3 = ((size_t)b*M_TOT + mb)*3;
        int i0 = g_nni[base3+0], i1 = g_nni[base3+1], i2 = g_nni[base3+2];
        float w0 = g_nnw[base3+0], w1w = g_nnw[base3+1], w2w = g_nnw[base3+2];
        float rx = g_rel[(size_t)m*3+0], ry = g_rel[(size_t)m*3+1], rz = g_rel[(size_t)m*3+2];
        const float* G0 = g_G + ((size_t)b*NN + i0)*128;
        const float* G1 = g_G + ((size_t)b*NN + i1)*128;
        const float* G2 = g_G + ((size_t)b*NN + i2)*128;
        int c0 = lane*4;
        float4 a  = *(const float4*)(G0 + c0);
        float4 bq = *(const float4*)(G1 + c0);
        float4 cq = *(const float4*)(G2 + c0);
        float va[4] = {a.x,a.y,a.z,a.w};
        float vb[4] = {bq.x,bq.y,bq.z,bq.w};
        float vc[4] = {cq.x,cq.y,cq.z,cq.w};
        #pragma unroll
        for (int j = 0; j < 4; j++) {
            int o = c0 + j;
            float acc = w0*va[j] + w1w*vb[j] + w2w*vc[j];
            acc = fmaf(rx, wr0[o], acc);
            acc = fmaf(ry, wr1[o], acc);
            acc = fmaf(rz, wr2[o], acc);
            tr[o][ml] = fmaxf(acc + sb[o], 0.0f);
        }
    }
    __syncthreads();
    // write h1T rows: 128 rows x 32 floats, 128B per row, coalesced
    int c = tid >> 1, base = (tid & 1)*16;
    float* dst = &g_h1T[(size_t)c*MG + m0 + base];
    #pragma unroll
    for (int q = 0; q < 4; q++) {
        float4 v = {tr[c][base+q*4+0], tr[c][base+q*4+1], tr[c][base+q*4+2], tr[c][base+q*4+3]};
        *(float4*)(dst + q*4) = v;
    }
}

// ---------------- gemm2 (tf32 tensor-core) + fused relu + maxpool over 64 ----------------
__global__ void __launch_bounds__(256) gemm2_pool_kernel(const float* __restrict__ bias)
{
    __shared__ float As[2][16][132];     // [k][m], padded
    __shared__ float Bs[2][16][68];      // [k][o], padded
    __shared__ int spool[128];           // [2 pool-groups][64 o]
    int m0 = blockIdx.x*128, o0 = blockIdx.y*64;
    int tid = threadIdx.x, lane = tid & 31, wid = tid >> 5;
    int wm = wid >> 1, wn = wid & 1;
    int kr = tid >> 4, c16 = tid & 15;
    if (tid < 128) spool[tid] = 0;

    float acc[2][4][4] = {};

    {
        const float* ap = &g_h1T[(size_t)kr*MG + m0 + c16*8];
        float4 a0 = *(const float4*)ap;
        float4 a1 = *(const float4*)(ap + 4);
        float* d = &As[0][kr][c16*8];
        d[0]=tf32r(a0.x); d[1]=tf32r(a0.y); d[2]=tf32r(a0.z); d[3]=tf32r(a0.w);
        d[4]=tf32r(a1.x); d[5]=tf32r(a1.y); d[6]=tf32r(a1.z); d[7]=tf32r(a1.w);
        float4 bv = *(const float4*)&g_w2T[kr*256 + o0 + c16*4];
        float* e = &Bs[0][kr][c16*4];
        e[0]=tf32r(bv.x); e[1]=tf32r(bv.y); e[2]=tf32r(bv.z); e[3]=tf32r(bv.w);
    }
    __syncthreads();

    int buf = 0;
    int lk = lane & 3, lr = lane >> 2;
    #pragma unroll 1
    for (int kb = 0; kb < 8; kb++) {
        bool has = kb < 7;
        float4 na0, na1, nb;
        if (has) {
            int kk = (kb+1)*16 + kr;
            const float* ap = &g_h1T[(size_t)kk*MG + m0 + c16*8];
            na0 = *(const float4*)ap;
            na1 = *(const float4*)(ap + 4);
            nb  = *(const float4*)&g_w2T[kk*256 + o0 + c16*4];
        }
        #pragma unroll
        for (int ks = 0; ks < 2; ks++) {
            int klo = ks*8 + lk;
            uint32_t afr[2][4];
            #pragma unroll
            for (int mt = 0; mt < 2; mt++) {
                int mr = wm*32 + mt*16 + lr;
                afr[mt][0] = __float_as_uint(As[buf][klo  ][mr]);
                afr[mt][1] = __float_as_uint(As[buf][klo  ][mr+8]);
                afr[mt][2] = __float_as_uint(As[buf][klo+4][mr]);
                afr[mt][3] = __float_as_uint(As[buf][klo+4][mr+8]);
            }
            uint32_t bfr[4][2];
            #pragma unroll
            for (int nt = 0; nt < 4; nt++) {
                int nr = wn*32 + nt*8 + lr;
                bfr[nt][0] = __float_as_uint(Bs[buf][klo  ][nr]);
                bfr[nt][1] = __float_as_uint(Bs[buf][klo+4][nr]);
            }
            #pragma unroll
            for (int mt = 0; mt < 2; mt++)
                #pragma unroll
                for (int nt = 0; nt < 4; nt++)
                    mma_tf32(acc[mt][nt], afr[mt], bfr[nt]);
        }
        if (has) {
            int nbuf = buf^1;
            float* d = &As[nbuf][kr][c16*8];
            d[0]=tf32r(na0.x); d[1]=tf32r(na0.y); d[2]=tf32r(na0.z); d[3]=tf32r(na0.w);
            d[4]=tf32r(na1.x); d[5]=tf32r(na1.y); d[6]=tf32r(na1.z); d[7]=tf32r(na1.w);
            float* e = &Bs[nbuf][kr][c16*4];
            e[0]=tf32r(nb.x); e[1]=tf32r(nb.y); e[2]=tf32r(nb.z); e[3]=tf32r(nb.w);
            __syncthreads();
            buf = nbuf;
        }
    }

    int grp = wm >> 1;
    #pragma unroll
    for (int nt = 0; nt < 4; nt++) {
        int c0 = wn*32 + nt*8 + (lane & 3)*2;
        float b0v = bias[o0 + c0], b1v = bias[o0 + c0 + 1];
        float p0v = 0.0f, p1v = 0.0f;
        #pragma unroll
        for (int mt = 0; mt < 2; mt++) {
            p0v = fmaxf(p0v, acc[mt][nt][0] + b0v);
            p0v = fmaxf(p0v, acc[mt][nt][2] + b0v);
            p1v = fmaxf(p1v, acc[mt][nt][1] + b1v);
            p1v = fmaxf(p1v, acc[mt][nt][3] + b1v);
        }
        atomicMax(&spool[grp*64 + c0],     __float_as_int(p0v));
        atomicMax(&spool[grp*64 + c0 + 1], __float_as_int(p1v));
    }
    __syncthreads();
    if (tid < 128) {
        int g = tid >> 6, ol = tid & 63;
        int b  = m0 >> 13;
        int p0 = (m0 >> 6) & 127;
        g_pool[((size_t)b*256 + o0 + ol)*NPT + p0 + g] = __int_as_float(spool[g*64 + ol]);
    }
}

// ---------------- fused linear + train-mode BN + relu ----------------
__global__ void lin_bn_kernel(const float* __restrict__ W, const float* __restrict__ bias,
                              const float* __restrict__ gam, const float* __restrict__ bet,
                              int stage)
{
    int o = blockIdx.x, tid = threadIdx.x;            // 256 threads = (b,p)
    int b = tid >> 7, p = tid & 127;
    int K = stage ? 128 : 256;
    const float* X = stage ? g_z0 : g_pool;
    __shared__ float ws[256];
    if (tid < K) ws[tid] = W[o*K + tid];
    __syncthreads();
    const float* Xb = X + (size_t)b*K*NPT + p;
    float acc = bias[o];
    #pragma unroll 8
    for (int c = 0; c < K; c++) acc = fmaf(ws[c], Xb[(size_t)c*NPT], acc);
    __shared__ float red[256];
    red[tid] = acc; __syncthreads();
    #pragma unroll
    for (int s = 128; s > 0; s >>= 1) { if (tid < s) red[tid] += red[tid+s]; __syncthreads(); }
    float mean = red[0] * (1.0f/256.0f);
    __syncthreads();
    float d = acc - mean;
    red[tid] = d*d; __syncthreads();
    #pragma unroll
    for (int s = 128; s > 0; s >>= 1) { if (tid < s) red[tid] += red[tid+s]; __syncthreads(); }
    float var = red[0] * (1.0f/256.0f);
    float z = d * rsqrtf(var + 1e-5f) * gam[o] + bet[o];
    float* Y = stage ? g_z1 : g_z0;
    Y[((size_t)b*128 + o)*NPT + p] = fmaxf(z, 0.0f);
}

__global__ void final_kernel(const float* __restrict__ W, const float* __restrict__ bias,
                             float* __restrict__ out)
{
    int b = blockIdx.x, p = threadIdx.x;
    const float* Z = g_z1 + (size_t)b*128*NPT;
    float acc = bias[0];
    #pragma unroll 8
    for (int c = 0; c < 128; c++) acc = fmaf(W[c], Z[(size_t)c*NPT + p], acc);
    out[b*NPT + p] = acc;
}

// ---------------- launch ----------------
extern "C" void kernel_launch(void* const* d_in, const int* in_sizes, int n_in,
                              void* d_out, int out_size)
{
    const float* oxyz  = (const float*)d_in[0];
    const float* ofeat = (const float*)d_in[1];
    const float* cand  = (const float*)d_in[2];
    // d_in[3] = pred_cls (unused)
    const float* poff  = (const float*)d_in[4];
    const float* pacls = (const float*)d_in[5];
    const float* pares = (const float*)d_in[6];
    const float* w1    = (const float*)d_in[7];
    const float* b1    = (const float*)d_in[8];
    const float* w2    = (const float*)d_in[9];
    const float* b2    = (const float*)d_in[10];
    const float* wi0   = (const float*)d_in[11];
    const float* bi0   = (const float*)d_in[12];
    const float* gi0   = (const float*)d_in[13];
    const float* bei0  = (const float*)d_in[14];
    const float* wi1   = (const float*)d_in[15];
    const float* bi1   = (const float*)d_in[16];
    const float* gi1   = (const float*)d_in[17];
    const float* bei1  = (const float*)d_in[18];
    const float* wi2   = (const float*)d_in[19];
    const float* bi2   = (const float*)d_in[20];
    float* out = (float*)d_out;

    setup_kernel<<<320, 256>>>(cand, poff, pacls, pares, oxyz, w1, w2);
    gemmG_kernel<<<dim3(64, 2, 2), 256>>>(ofeat);
    three_nn_kernel<<<1024, 256>>>(oxyz);
    combine_kernel<<<512, 256>>>(w1, b1);
    gemm2_pool_kernel<<<dim3(128, 4), 256>>>(b2);
    lin_bn_kernel<<<128, 256>>>(wi0, bi0, gi0, bei0, 0);
    lin_bn_kernel<<<128, 256>>>(wi1, bi1, gi1, bei1, 1);
    final_kernel<<<2, 128>>>(wi2, bi2, out);
}